// round 12
// baseline (speedup 1.0000x reference)
#include <cuda_runtime.h>
#include <cuda_bf16.h>
#include <cstdint>

#define NN 100000
#define EE 800000
#define QMM 32
#define BB 100
#define LL 4
#define EPS_BN 1e-5f
#define SLOTMAX 812800          // >= EE + 127*BB
#define MAXT 6350               // SLOTMAX / 128

// edge kernel smem: 2 stages x (A 128x144 + B 64x144) = 2 x 27648 = 55296 bytes
#define STG 27648
#define OB 18432                // B offset within a stage
#define SMEM_EDGE 55296
#define OD 0                    // D overlay (128 x 272B = 34816B) over dead stage bufs

// ---------------- scratch ----------------
__device__ __nv_bfloat16 g_A1h[(size_t)SLOTMAX * 64];
__device__ __nv_bfloat16 g_A1l[(size_t)SLOTMAX * 64];
__device__ __nv_bfloat16 g_A2h[(size_t)SLOTMAX * 64];
__device__ __nv_bfloat16 g_A2l[(size_t)SLOTMAX * 64];
__device__ __nv_bfloat16 g_B1h4[(size_t)LL * BB * 4096];   // per-layer per-graph W1b hi
__device__ __nv_bfloat16 g_B1l4[(size_t)LL * BB * 4096];
__device__ __nv_bfloat16 g_B2h4[LL * 4096];
__device__ __nv_bfloat16 g_B2l4[LL * 4096];
__device__ int   g_ssrc[SLOTMAX];
__device__ int   g_sdst[SLOTMAX];
__device__ int   g_gcnt[128], g_gcur[128];
__device__ int   g_tile_g[MAXT];
__device__ int   g_flag;
__device__ float g_agg[(size_t)NN * 64];
__device__ float g_y1[(size_t)NN * 64];
__device__ float g_y2[(size_t)NN * 64];
__device__ float g_wtab4[LL * BB * QMM];
__device__ float g_Wc4[LL * 128 * 64];
__device__ float g_bc4[LL * 64];
__device__ float g_stats[256];
__device__ float g_bnsc[64], g_bnsh[64];   // fused BN2 scale/shift for next layer's x

// ---------------- helpers ----------------
__device__ __forceinline__ unsigned long long pack2(float a, float b) {
    unsigned long long r;
    asm("mov.b64 %0, {%1, %2};" : "=l"(r) : "f"(a), "f"(b));
    return r;
}
__device__ __forceinline__ void ffma2(unsigned long long& d, unsigned long long a, unsigned long long b) {
    asm("fma.rn.f32x2 %0, %1, %2, %0;" : "+l"(d) : "l"(a), "l"(b));
}
__device__ __forceinline__ float2 unpack2(unsigned long long v) {
    float2 r;
    asm("mov.b64 {%0, %1}, %2;" : "=f"(r.x), "=f"(r.y) : "l"(v));
    return r;
}
__device__ __forceinline__ void red_add_v4(float* p, float a, float b, float c, float d) {
    asm volatile("red.global.add.v4.f32 [%0], {%1, %2, %3, %4};"
                 :: "l"(p), "f"(a), "f"(b), "f"(c), "f"(d) : "memory");
}
__device__ __forceinline__ void mma16816(float* c, const uint32_t* a, const uint32_t* b) {
    asm volatile(
        "mma.sync.aligned.m16n8k16.row.col.f32.bf16.bf16.f32 "
        "{%0,%1,%2,%3}, {%4,%5,%6,%7}, {%8,%9}, {%0,%1,%2,%3};"
        : "+f"(c[0]), "+f"(c[1]), "+f"(c[2]), "+f"(c[3])
        : "r"(a[0]), "r"(a[1]), "r"(a[2]), "r"(a[3]), "r"(b[0]), "r"(b[1]));
}
__device__ __forceinline__ uint32_t smem_u32(const void* p) {
    uint32_t a;
    asm("{ .reg .u64 t; cvta.to.shared.u64 t, %1; cvt.u32.u64 %0, t; }" : "=r"(a) : "l"(p));
    return a;
}
__device__ __forceinline__ void ldsm4(uint32_t* r, uint32_t a) {
    asm volatile("ldmatrix.sync.aligned.m8n8.x4.shared.b16 {%0,%1,%2,%3}, [%4];"
                 : "=r"(r[0]), "=r"(r[1]), "=r"(r[2]), "=r"(r[3]) : "r"(a));
}
__device__ __forceinline__ void cp16(uint32_t d, const void* s) {
    asm volatile("cp.async.cg.shared.global [%0], [%1], 16;" :: "r"(d), "l"(s) : "memory");
}
__device__ __forceinline__ void cp_commit() { asm volatile("cp.async.commit_group;" ::: "memory"); }

__device__ __forceinline__ void product(float (&acc)[2][4][4], uint32_t aB, uint32_t bB) {
#pragma unroll
    for (int kc = 0; kc < 4; kc++) {
        uint32_t a0[4], a1[4], b0[4], b1[4];
        ldsm4(a0, aB + kc * 32);
        ldsm4(a1, aB + 16 * 144 + kc * 32);
        ldsm4(b0, bB + kc * 32);
        ldsm4(b1, bB + 16 * 144 + kc * 32);
        mma16816(acc[0][0], a0, b0);
        mma16816(acc[0][1], a0, b0 + 2);
        mma16816(acc[0][2], a0, b1);
        mma16816(acc[0][3], a0, b1 + 2);
        mma16816(acc[1][0], a1, b0);
        mma16816(acc[1][1], a1, b0 + 2);
        mma16816(acc[1][2], a1, b1);
        mma16816(acc[1][3], a1, b1 + 2);
    }
}

// ---------------- K1: setup + all-layer prep (launch #1) ----------------
__global__ void k1_setup(const float* __restrict__ Lam, const float* __restrict__ pw1,
                         const float* __restrict__ pb1, const float* __restrict__ pw2,
                         const float* __restrict__ pb2,
                         const float* __restrict__ enc_w, const float* __restrict__ enc_b,
                         const float* __restrict__ lin_w, const float* __restrict__ lin_b) {
    int bid = blockIdx.x, t = threadIdx.x;
    size_t i = (size_t)bid * 256 + t;
    ((float4*)g_agg)[i] = make_float4(0.f, 0.f, 0.f, 0.f);
    if (i < SLOTMAX) g_ssrc[i] = -1;
    if (bid == 0) {
        g_stats[t] = 0.f;
        if (t < 128) g_gcnt[t] = 0;
        if (t == 0) g_flag = 0;
    }
    if (bid >= 4000 && bid < 4256 && t < 64) {
        int idx = bid - 4000;
        int l = idx >> 6, k = idx & 63, hh = t;
        const float* ew = enc_w + (size_t)l * 4096;
        const float* lw = lin_w + (size_t)l * 4096;
        float s = 0.f;
        for (int j = 0; j < 64; j++) s += ew[k * 64 + j] * lw[j * 64 + hh];
        g_Wc4[l * 8192 + k * 64 + hh] = s;
        g_Wc4[l * 8192 + (64 + k) * 64 + hh] = lw[k * 64 + hh];
        if (k == 0) {
            float bias = lin_b[l * 64 + hh];
            for (int j = 0; j < 64; j++) bias += enc_b[l * 64 + j] * lw[j * 64 + hh];
            g_bc4[l * 64 + hh] = bias;
        }
    }
    if (bid >= 4300 && bid < 4350) {
        int idx = (bid - 4300) * 256 + t;   // < 12800
        int l = idx / 3200, j = idx % 3200;
        float lam = Lam[j];
        float s = pb2[l];
#pragma unroll
        for (int jj = 0; jj < 16; jj++) {
            float h = fmaxf(lam * pw1[l * 16 + jj] + pb1[l * 16 + jj], 0.f);
            s += h * pw2[l * 16 + jj];
        }
        g_wtab4[idx] = s;
    }
}

// ---------------- K2: count + all-layer weight bf16 prep (launch #2) ----------------
__global__ void k2_count_wprep(const int* __restrict__ ei, const int* __restrict__ batch) {
    int bid = blockIdx.x, t = threadIdx.x;
    if (bid < 3125) {
        int e = bid * 256 + t;
        if (e < EE) atomicAdd(&g_gcnt[batch[ei[e]]], 1);
        return;
    }
    int idx = bid - 3125;          // 0..403
    int l = idx / 101, sub = idx % 101;
    if (sub < BB) {
        size_t base = ((size_t)l * BB + sub) * 4096;
#pragma unroll 4
        for (int i = 0; i < 16; i++) {
            int p = i * 256 + t;
            int c = p >> 6, k = p & 63;
            float w = g_wtab4[l * 3200 + sub * 32 + (k & 31)] * g_Wc4[l * 8192 + k * 64 + c];
            __nv_bfloat16 h = __float2bfloat16(w);
            g_B1h4[base + p] = h;
            g_B1l4[base + p] = __float2bfloat16(w - __bfloat162float(h));
        }
    } else {
#pragma unroll 4
        for (int i = 0; i < 16; i++) {
            int p = i * 256 + t;
            int c = p >> 6, k = p & 63;
            float w = g_Wc4[l * 8192 + (64 + k) * 64 + c];
            __nv_bfloat16 h = __float2bfloat16(w);
            g_B2h4[l * 4096 + p] = h;
            g_B2l4[l * 4096 + p] = __float2bfloat16(w - __bfloat162float(h));
        }
    }
}

// ---------------- K3: scan (block 0) + fill + convert (launch #3) ----------------
__global__ __launch_bounds__(256) void k3_scan_fill_convert(const float* __restrict__ pe,
                                                            const float* __restrict__ edge_attr,
                                                            const int* __restrict__ ei,
                                                            const int* __restrict__ batch) {
    __shared__ int sNT[128];
    __shared__ int sTot;
    int t = threadIdx.x;
    if (blockIdx.x == 0) {
        int nt = 0;
        if (t < 128) {
            int cnt = (t < BB) ? g_gcnt[t] : 0;
            nt = (cnt + 127) >> 7;
            sNT[t] = nt;
        }
        __syncthreads();
        for (int off = 1; off < 128; off <<= 1) {
            int v = (t >= off && t < 128) ? sNT[t - off] : 0;
            __syncthreads();
            if (t < 128) sNT[t] += v;
            __syncthreads();
        }
        if (t < BB) {
            int excl = sNT[t] - nt;
            g_gcur[t] = excl * 128;
            for (int j = 0; j < nt; j++) g_tile_g[excl + j] = t;
        }
        if (t == 127) sTot = sNT[127];
        __syncthreads();
        for (int i = sTot + t; i < MAXT; i += 256) g_tile_g[i] = -1;
        __threadfence();
        __syncthreads();
        if (t == 0) atomicExch(&g_flag, 1);
    } else {
        if (t == 0) {
            while (atomicAdd(&g_flag, 0) == 0) __nanosleep(64);
        }
        __syncthreads();
    }

    int e = blockIdx.x * 8 + (t >> 5);
    int qm = t & 31;
    int src = ei[e];
    int dst = ei[EE + e];
    int slot = 0;
    if (qm == 0) slot = atomicAdd(&g_gcur[batch[src]], 1);
    slot = __shfl_sync(0xffffffffu, slot, 0);

    const float2* pe2 = (const float2*)pe;
    float2 zs = pe2[(size_t)src * 32 + qm];
    float2 zd = pe2[(size_t)dst * 32 + qm];
    float zr = zs.x * zd.x + zs.y * zd.y;
    float zi = zs.y * zd.x - zs.x * zd.y;
    size_t base = (size_t)slot * 64;
    __nv_bfloat16 h;
    h = __float2bfloat16(zr); g_A1h[base + qm] = h;
    g_A1l[base + qm] = __float2bfloat16(zr - __bfloat162float(h));
    h = __float2bfloat16(zi); g_A1h[base + 32 + qm] = h;
    g_A1l[base + 32 + qm] = __float2bfloat16(zi - __bfloat162float(h));
    float a0 = edge_attr[(size_t)e * 64 + qm];
    float a1 = edge_attr[(size_t)e * 64 + 32 + qm];
    h = __float2bfloat16(a0); g_A2h[base + qm] = h;
    g_A2l[base + qm] = __float2bfloat16(a0 - __bfloat162float(h));
    h = __float2bfloat16(a1); g_A2h[base + 32 + qm] = h;
    g_A2l[base + 32 + qm] = __float2bfloat16(a1 - __bfloat162float(h));
    if (qm == 0) { g_ssrc[slot] = src; g_sdst[slot] = dst; }
}

// ---------------- edge kernel: K=384 double-buffered HMMA ----------------
// xsrc = raw x (l=0, use_bn=0) or g_y2 of previous layer (use_bn=1: apply relu(y*sc+sh)).
__global__ __launch_bounds__(256, 3) void edge_mma_kernel(const float* __restrict__ xsrc,
                                                          int l, int use_bn) {
    extern __shared__ char sm[];
    uint32_t sb = smem_u32(sm);
    int t = threadIdx.x;
    int lane = t & 31, w = t >> 5;
    if (blockIdx.x == 0) g_stats[t] = 0.f;
    int tile = blockIdx.x;
    int b = g_tile_g[tile];
    if (b < 0) return;

    size_t bbase = ((size_t)l * BB + b) * 4096;
    const __nv_bfloat16* As[6] = {
        g_A1h + (size_t)tile * 8192, g_A1l + (size_t)tile * 8192,
        g_A1h + (size_t)tile * 8192, g_A2h + (size_t)tile * 8192,
        g_A2l + (size_t)tile * 8192, g_A2h + (size_t)tile * 8192};
    const __nv_bfloat16* Bs[6] = {
        g_B1h4 + bbase, g_B1h4 + bbase, g_B1l4 + bbase,
        g_B2h4 + l * 4096, g_B2h4 + l * 4096, g_B2l4 + l * 4096};

#define STAGE(s) { \
    uint32_t o = sb + ((s) & 1) * STG; \
    const char* ga = (const char*)As[s]; \
    const char* gb = (const char*)Bs[s]; \
    _Pragma("unroll") \
    for (int i = 0; i < 4; i++) { \
        int lin = i * 256 + t; \
        cp16(o + (lin >> 3) * 144 + (lin & 7) * 16, ga + lin * 16); } \
    _Pragma("unroll") \
    for (int i = 0; i < 2; i++) { \
        int lin = i * 256 + t; \
        cp16(o + OB + (lin >> 3) * 144 + (lin & 7) * 16, gb + lin * 16); } \
    cp_commit(); }

    STAGE(0);
    STAGE(1);

    uint32_t aOff = (uint32_t)((w & 3) * 32 + (lane & 15)) * 144 + ((lane >> 4) & 1) * 16;
    uint32_t bOff = OB + (uint32_t)((w >> 2) * 32 + ((lane >> 4) & 1) * 8 + (lane & 7)) * 144
                  + ((lane >> 3) & 1) * 16;

    float acc[2][4][4];
#pragma unroll
    for (int mt = 0; mt < 2; mt++)
#pragma unroll
        for (int nt = 0; nt < 4; nt++)
#pragma unroll
            for (int j = 0; j < 4; j++) acc[mt][nt][j] = 0.f;

#pragma unroll
    for (int s = 0; s < 6; s++) {
        if (s < 5) { asm volatile("cp.async.wait_group 1;" ::: "memory"); }
        else       { asm volatile("cp.async.wait_group 0;" ::: "memory"); }
        __syncthreads();
        uint32_t o = sb + (s & 1) * STG;
        product(acc, o + aOff, o + bOff);
        __syncthreads();
        if (s + 2 < 6) STAGE(s + 2);
    }

    // ---- write D frags (row stride 272B), overlay stage buffers ----
    int wm = w & 3, wn = w >> 2;
    int g = lane >> 2, tig = lane & 3;
#pragma unroll
    for (int mt = 0; mt < 2; mt++) {
        int r0 = wm * 32 + mt * 16 + g;
#pragma unroll
        for (int nt = 0; nt < 4; nt++) {
            int c = wn * 32 + nt * 8 + tig * 2;
            *(float2*)(sm + OD + r0 * 272 + c * 4) = make_float2(acc[mt][nt][0], acc[mt][nt][1]);
            *(float2*)(sm + OD + (r0 + 8) * 272 + c * 4) = make_float2(acc[mt][nt][2], acc[mt][nt][3]);
        }
    }
    __syncthreads();

    // ---- epilogue: 2 threads per edge; fused BN on x gather ----
    int edge = t >> 1, half = t & 1;
    int slot = tile * 128 + edge;
    int srcn = g_ssrc[slot];
    if (srcn >= 0) {
        int dstn = g_sdst[slot];
        const float* Dr = (const float*)(sm + OD + edge * 272 + half * 128);
        const float* xr = xsrc + (size_t)srcn * 64 + half * 32;
        const float* br = g_bc4 + l * 64 + half * 32;
        const float* scp = g_bnsc + half * 32;
        const float* shp = g_bnsh + half * 32;
        float* dp = g_agg + (size_t)dstn * 64 + half * 32;
#pragma unroll
        for (int q = 0; q < 8; q++) {
            float4 dv = *(const float4*)(Dr + q * 4);
            float4 xv = *(const float4*)(xr + q * 4);
            if (use_bn) {
                float4 sc = *(const float4*)(scp + q * 4);
                float4 sh = *(const float4*)(shp + q * 4);
                xv.x = fmaxf(xv.x * sc.x + sh.x, 0.f);
                xv.y = fmaxf(xv.y * sc.y + sh.y, 0.f);
                xv.z = fmaxf(xv.z * sc.z + sh.z, 0.f);
                xv.w = fmaxf(xv.w * sc.w + sh.w, 0.f);
            }
            float4 bc = *(const float4*)(br + q * 4);
            red_add_v4(dp + q * 4,
                       fmaxf(dv.x + bc.x + xv.x, 0.f), fmaxf(dv.y + bc.y + xv.y, 0.f),
                       fmaxf(dv.z + bc.z + xv.z, 0.f), fmaxf(dv.w + bc.w + xv.w, 0.f));
        }
    }
}

// ---------------- node kernels ----------------
__global__ __launch_bounds__(256) void nodeA_kernel(const float* __restrict__ xsrc,
                                                    const float* __restrict__ W,
                                                    const float* __restrict__ bias,
                                                    int l, int use_bn) {
    __shared__ float sW[64 * 64];
    __shared__ float sA[64 * 32];
    __shared__ float sRs[256], sRq[256];
    int t = threadIdx.x;
    int n0 = blockIdx.x * 32;
    {
        const float4* Wv = (const float4*)(W + (size_t)l * 4096);
        float4* sWv = (float4*)sW;
#pragma unroll
        for (int i = 0; i < 4; i++) sWv[t + 256 * i] = Wv[t + 256 * i];
    }
    int n_loc = t & 31, part = t >> 5;
    int k0 = part * 8;
    {
        size_t base = (size_t)(n0 + n_loc) * 64 + k0;
        float4 x0 = *(const float4*)(xsrc + base);
        float4 x1 = *(const float4*)(xsrc + base + 4);
        if (use_bn) {
            float4 sc0 = *(const float4*)(g_bnsc + k0);
            float4 sc1 = *(const float4*)(g_bnsc + k0 + 4);
            float4 sh0 = *(const float4*)(g_bnsh + k0);
            float4 sh1 = *(const float4*)(g_bnsh + k0 + 4);
            x0.x = fmaxf(x0.x * sc0.x + sh0.x, 0.f);
            x0.y = fmaxf(x0.y * sc0.y + sh0.y, 0.f);
            x0.z = fmaxf(x0.z * sc0.z + sh0.z, 0.f);
            x0.w = fmaxf(x0.w * sc0.w + sh0.w, 0.f);
            x1.x = fmaxf(x1.x * sc1.x + sh1.x, 0.f);
            x1.y = fmaxf(x1.y * sc1.y + sh1.y, 0.f);
            x1.z = fmaxf(x1.z * sc1.z + sh1.z, 0.f);
            x1.w = fmaxf(x1.w * sc1.w + sh1.w, 0.f);
        }
        float4 a0 = *(const float4*)(g_agg + base);
        float4 a1 = *(const float4*)(g_agg + base + 4);
        *(float4*)(g_agg + base) = make_float4(0.f, 0.f, 0.f, 0.f);
        *(float4*)(g_agg + base + 4) = make_float4(0.f, 0.f, 0.f, 0.f);
        sA[(k0 + 0) * 32 + n_loc] = x0.x + a0.x;
        sA[(k0 + 1) * 32 + n_loc] = x0.y + a0.y;
        sA[(k0 + 2) * 32 + n_loc] = x0.z + a0.z;
        sA[(k0 + 3) * 32 + n_loc] = x0.w + a0.w;
        sA[(k0 + 4) * 32 + n_loc] = x1.x + a1.x;
        sA[(k0 + 5) * 32 + n_loc] = x1.y + a1.y;
        sA[(k0 + 6) * 32 + n_loc] = x1.z + a1.z;
        sA[(k0 + 7) * 32 + n_loc] = x1.w + a1.w;
    }
    __syncthreads();

    int tx = t & 63, ty = t >> 6;
    unsigned long long acc[4] = {0ull, 0ull, 0ull, 0ull};
#pragma unroll 8
    for (int k = 0; k < 64; k++) {
        float w = sW[k * 64 + tx];
        unsigned long long w2 = pack2(w, w);
        const ulonglong2* ap = (const ulonglong2*)(sA + k * 32 + ty * 8);
        ulonglong2 a01 = ap[0];
        ulonglong2 a23 = ap[1];
        ffma2(acc[0], a01.x, w2);
        ffma2(acc[1], a01.y, w2);
        ffma2(acc[2], a23.x, w2);
        ffma2(acc[3], a23.y, w2);
    }
    float bb = bias[l * 64 + tx];
    float s = 0.f, q = 0.f;
#pragma unroll
    for (int p = 0; p < 4; p++) {
        float2 v = unpack2(acc[p]);
        int na = ty * 8 + p * 2;
        float yA = v.x + bb, yB = v.y + bb;
        g_y1[(size_t)(n0 + na) * 64 + tx] = yA;
        g_y1[(size_t)(n0 + na + 1) * 64 + tx] = yB;
        s += yA + yB;
        q += yA * yA + yB * yB;
    }
    sRs[t] = s;
    sRq[t] = q;
    __syncthreads();
    if (t < 64) {
        s = sRs[t] + sRs[64 + t] + sRs[128 + t] + sRs[192 + t];
        q = sRq[t] + sRq[64 + t] + sRq[128 + t] + sRq[192 + t];
        atomicAdd(&g_stats[t], s);
        atomicAdd(&g_stats[64 + t], q);
    }
}

__global__ __launch_bounds__(256) void nodeB_kernel(const float* __restrict__ W,
                                                    const float* __restrict__ bias,
                                                    const float* __restrict__ bg,
                                                    const float* __restrict__ bnb, int l) {
    __shared__ float sW[64 * 64];
    __shared__ float sA[64 * 32];
    __shared__ float sSc[64], sSh[64];
    __shared__ float sRs[256], sRq[256];
    int t = threadIdx.x;
    int n0 = blockIdx.x * 32;
    {
        const float4* Wv = (const float4*)(W + (size_t)l * 4096);
        float4* sWv = (float4*)sW;
#pragma unroll
        for (int i = 0; i < 4; i++) sWv[t + 256 * i] = Wv[t + 256 * i];
    }
    if (t < 64) {
        float mu = g_stats[t] * (1.0f / NN);
        float var = g_stats[64 + t] * (1.0f / NN) - mu * mu;
        float rs = rsqrtf(var + EPS_BN);
        float sc = rs * bg[l * 64 + t];
        sSc[t] = sc;
        sSh[t] = bnb[l * 64 + t] - mu * sc;
    }
    __syncthreads();
    int n_loc = t & 31, part = t >> 5;
    int k0 = part * 8;
    {
        size_t base = (size_t)(n0 + n_loc) * 64 + k0;
        float4 y0 = *(const float4*)(g_y1 + base);
        float4 y1v = *(const float4*)(g_y1 + base + 4);
        sA[(k0 + 0) * 32 + n_loc] = fmaxf(y0.x * sSc[k0 + 0] + sSh[k0 + 0], 0.f);
        sA[(k0 + 1) * 32 + n_loc] = fmaxf(y0.y * sSc[k0 + 1] + sSh[k0 + 1], 0.f);
        sA[(k0 + 2) * 32 + n_loc] = fmaxf(y0.z * sSc[k0 + 2] + sSh[k0 + 2], 0.f);
        sA[(k0 + 3) * 32 + n_loc] = fmaxf(y0.w * sSc[k0 + 3] + sSh[k0 + 3], 0.f);
        sA[(k0 + 4) * 32 + n_loc] = fmaxf(y1v.x * sSc[k0 + 4] + sSh[k0 + 4], 0.f);
        sA[(k0 + 5) * 32 + n_loc] = fmaxf(y1v.y * sSc[k0 + 5] + sSh[k0 + 5], 0.f);
        sA[(k0 + 6) * 32 + n_loc] = fmaxf(y1v.z * sSc[k0 + 6] + sSh[k0 + 6], 0.f);
        sA[(k0 + 7) * 32 + n_loc] = fmaxf(y1v.w * sSc[k0 + 7] + sSh[k0 + 7], 0.f);
    }
    __syncthreads();

    int tx = t & 63, ty = t >> 6;
    unsigned long long acc[4] = {0ull, 0ull, 0ull, 0ull};
#pragma unroll 8
    for (int k = 0; k < 64; k++) {
        float w = sW[k * 64 + tx];
        unsigned long long w2 = pack2(w, w);
        const ulonglong2* ap = (const ulonglong2*)(sA + k * 32 + ty * 8);
        ulonglong2 a01 = ap[0];
        ulonglong2 a23 = ap[1];
        ffma2(acc[0], a01.x, w2);
        ffma2(acc[1], a01.y, w2);
        ffma2(acc[2], a23.x, w2);
        ffma2(acc[3], a23.y, w2);
    }
    float bb = bias[l * 64 + tx];
    float s = 0.f, q = 0.f;
#pragma unroll
    for (int p = 0; p < 4; p++) {
        float2 v = unpack2(acc[p]);
        int na = ty * 8 + p * 2;
        float yA = v.x + bb, yB = v.y + bb;
        g_y2[(size_t)(n0 + na) * 64 + tx] = yA;
        g_y2[(size_t)(n0 + na + 1) * 64 + tx] = yB;
        s += yA + yB;
        q += yA * yA + yB * yB;
    }
    sRs[t] = s;
    sRq[t] = q;
    __syncthreads();
    if (t < 64) {
        s = sRs[t] + sRs[64 + t] + sRs[128 + t] + sRs[192 + t];
        q = sRq[t] + sRq[64 + t] + sRq[128 + t] + sRq[192 + t];
        atomicAdd(&g_stats[128 + t], s);
        atomicAdd(&g_stats[192 + t], q);
    }
}

// tiny: derive sc/sh from BN2 stats for fused application next layer
__global__ void bnsc_kernel(const float* __restrict__ bg, const float* __restrict__ bnb, int l) {
    int t = threadIdx.x;   // 64
    float mu = g_stats[128 + t] * (1.0f / NN);
    float var = g_stats[192 + t] * (1.0f / NN) - mu * mu;
    float rs = rsqrtf(var + EPS_BN);
    float sc = rs * bg[l * 64 + t];
    g_bnsc[t] = sc;
    g_bnsh[t] = bnb[l * 64 + t] - mu * sc;
}

// final-layer BN2 apply (no relu) writing the output
__global__ void bn_apply_kernel(const float* __restrict__ bg, const float* __restrict__ bnb,
                                float* __restrict__ xout, int l) {
    int i = blockIdx.x * 256 + threadIdx.x;
    int h = i & 63;
    float mu = g_stats[128 + h] * (1.0f / NN);
    float var = g_stats[192 + h] * (1.0f / NN) - mu * mu;
    float rs = rsqrtf(var + EPS_BN);
    float sc = rs * bg[l * 64 + h];
    float sh = bnb[l * 64 + h] - mu * sc;
    xout[i] = g_y2[i] * sc + sh;
}

__global__ void copy_pe_kernel(const float* __restrict__ pe, float* __restrict__ out) {
    size_t i = (size_t)blockIdx.x * 256 + threadIdx.x;
    ((float4*)out)[i] = ((const float4*)pe)[i];
}

// ---------------- launcher ----------------
extern "C" void kernel_launch(void* const* d_in, const int* in_sizes, int n_in,
                              void* d_out, int out_size) {
    const float* x        = (const float*)d_in[0];
    const float* pe       = (const float*)d_in[1];
    const float* Lam      = (const float*)d_in[2];
    const float* edge_attr= (const float*)d_in[3];
    const float* pw1      = (const float*)d_in[4];
    const float* pb1      = (const float*)d_in[5];
    const float* pw2      = (const float*)d_in[6];
    const float* pb2      = (const float*)d_in[7];
    const float* enc_w    = (const float*)d_in[8];
    const float* enc_b    = (const float*)d_in[9];
    const float* lin_w    = (const float*)d_in[10];
    const float* lin_b    = (const float*)d_in[11];
    const float* mw1      = (const float*)d_in[12];
    const float* mb1      = (const float*)d_in[13];
    const float* bn1g     = (const float*)d_in[14];
    const float* bn1b     = (const float*)d_in[15];
    const float* mw2      = (const float*)d_in[16];
    const float* mb2      = (const float*)d_in[17];
    const float* bn2g     = (const float*)d_in[18];
    const float* bn2b     = (const float*)d_in[19];
    const int*   ei       = (const int*)d_in[20];
    const int*   batch    = (const int*)d_in[21];
    float* out = (float*)d_out;

    float* y2 = nullptr;
    cudaGetSymbolAddress((void**)&y2, g_y2);
    cudaFuncSetAttribute(edge_mma_kernel, cudaFuncAttributeMaxDynamicSharedMemorySize, SMEM_EDGE);

    k1_setup<<<6250, 256>>>(Lam, pw1, pb1, pw2, pb2, enc_w, enc_b, lin_w, lin_b);
    k2_count_wprep<<<3125 + 404, 256>>>(ei, batch);
    k3_scan_fill_convert<<<EE / 8, 256>>>(pe, edge_attr, ei, batch);

    for (int l = 0; l < LL; l++) {
        const float* xsrc = (l == 0) ? x : (const float*)y2;
        int use_bn = (l != 0);
        edge_mma_kernel<<<MAXT, 256, SMEM_EDGE>>>(xsrc, l, use_bn);
        nodeA_kernel<<<NN / 32, 256>>>(xsrc, mw1, mb1, l, use_bn);
        nodeB_kernel<<<NN / 32, 256>>>(mw2, mb2, bn1g, bn1b, l);
        if (l != LL - 1) {
            bnsc_kernel<<<1, 64>>>(bn2g, bn2b, l);
        } else {
            bn_apply_kernel<<<NN * 64 / 256, 256>>>(bn2g, bn2b, out, l);
        }
    }
    if (out_size >= (int)(2u * NN * 64)) {
        copy_pe_kernel<<<NN * 16 / 256, 256>>>(pe, out + (size_t)NN * 64);
    }
}

// round 13
// speedup vs baseline: 1.0152x; 1.0152x over previous
#include <cuda_runtime.h>
#include <cuda_bf16.h>
#include <cstdint>

#define NN 100000
#define EE 800000
#define QMM 32
#define BB 100
#define LL 4
#define EPS_BN 1e-5f
#define SLOTMAX 812800          // >= EE + 127*BB
#define MAXT 6350               // SLOTMAX / 128

// edge kernel smem: A0,A1 (18432 each) + B0,B1 (9216 each) = 55296 bytes
#define OA0 0
#define OA1 18432
#define OB0 36864
#define OB1 46080
#define SMEM_EDGE 55296
#define OD 0                    // D overlay (128 x 272B = 34816B) over dead A bufs

// ---------------- scratch ----------------
__device__ __nv_bfloat16 g_A1h[(size_t)SLOTMAX * 64];
__device__ __nv_bfloat16 g_A1l[(size_t)SLOTMAX * 64];
__device__ __nv_bfloat16 g_A2h[(size_t)SLOTMAX * 64];
__device__ __nv_bfloat16 g_A2l[(size_t)SLOTMAX * 64];
__device__ __nv_bfloat16 g_B1h4[(size_t)LL * BB * 4096];   // per-layer per-graph W1b hi
__device__ __nv_bfloat16 g_B1l4[(size_t)LL * BB * 4096];
__device__ __nv_bfloat16 g_B2h4[LL * 4096];
__device__ __nv_bfloat16 g_B2l4[LL * 4096];
__device__ int   g_ssrc[SLOTMAX];
__device__ int   g_sdst[SLOTMAX];
__device__ int   g_gcnt[128], g_gcur[128];
__device__ int   g_tile_g[MAXT];
__device__ int   g_flag;
__device__ float g_agg[(size_t)NN * 64];
__device__ float g_y1[(size_t)NN * 64];
__device__ float g_y2[(size_t)NN * 64];
__device__ float g_wtab4[LL * BB * QMM];
__device__ float g_Wc4[LL * 128 * 64];
__device__ float g_bc4[LL * 64];
__device__ float g_stats[256];
__device__ float g_bnsc[64], g_bnsh[64];   // fused BN2 scale/shift for next layer's x

// ---------------- helpers ----------------
__device__ __forceinline__ unsigned long long pack2(float a, float b) {
    unsigned long long r;
    asm("mov.b64 %0, {%1, %2};" : "=l"(r) : "f"(a), "f"(b));
    return r;
}
__device__ __forceinline__ void ffma2(unsigned long long& d, unsigned long long a, unsigned long long b) {
    asm("fma.rn.f32x2 %0, %1, %2, %0;" : "+l"(d) : "l"(a), "l"(b));
}
__device__ __forceinline__ float2 unpack2(unsigned long long v) {
    float2 r;
    asm("mov.b64 {%0, %1}, %2;" : "=f"(r.x), "=f"(r.y) : "l"(v));
    return r;
}
__device__ __forceinline__ void red_add_v4(float* p, float a, float b, float c, float d) {
    asm volatile("red.global.add.v4.f32 [%0], {%1, %2, %3, %4};"
                 :: "l"(p), "f"(a), "f"(b), "f"(c), "f"(d) : "memory");
}
__device__ __forceinline__ void mma16816(float* c, const uint32_t* a, const uint32_t* b) {
    asm volatile(
        "mma.sync.aligned.m16n8k16.row.col.f32.bf16.bf16.f32 "
        "{%0,%1,%2,%3}, {%4,%5,%6,%7}, {%8,%9}, {%0,%1,%2,%3};"
        : "+f"(c[0]), "+f"(c[1]), "+f"(c[2]), "+f"(c[3])
        : "r"(a[0]), "r"(a[1]), "r"(a[2]), "r"(a[3]), "r"(b[0]), "r"(b[1]));
}
__device__ __forceinline__ uint32_t smem_u32(const void* p) {
    uint32_t a;
    asm("{ .reg .u64 t; cvta.to.shared.u64 t, %1; cvt.u32.u64 %0, t; }" : "=r"(a) : "l"(p));
    return a;
}
__device__ __forceinline__ void ldsm4(uint32_t* r, uint32_t a) {
    asm volatile("ldmatrix.sync.aligned.m8n8.x4.shared.b16 {%0,%1,%2,%3}, [%4];"
                 : "=r"(r[0]), "=r"(r[1]), "=r"(r[2]), "=r"(r[3]) : "r"(a));
}
__device__ __forceinline__ void cp16(uint32_t d, const void* s) {
    asm volatile("cp.async.cg.shared.global [%0], [%1], 16;" :: "r"(d), "l"(s) : "memory");
}
__device__ __forceinline__ void cp_commit() { asm volatile("cp.async.commit_group;" ::: "memory"); }

__device__ __forceinline__ void product(float (&acc)[2][4][4], uint32_t aB, uint32_t bB) {
#pragma unroll
    for (int kc = 0; kc < 4; kc++) {
        uint32_t a0[4], a1[4], b0[4], b1[4];
        ldsm4(a0, aB + kc * 32);
        ldsm4(a1, aB + 16 * 144 + kc * 32);
        ldsm4(b0, bB + kc * 32);
        ldsm4(b1, bB + 16 * 144 + kc * 32);
        mma16816(acc[0][0], a0, b0);
        mma16816(acc[0][1], a0, b0 + 2);
        mma16816(acc[0][2], a0, b1);
        mma16816(acc[0][3], a0, b1 + 2);
        mma16816(acc[1][0], a1, b0);
        mma16816(acc[1][1], a1, b0 + 2);
        mma16816(acc[1][2], a1, b1);
        mma16816(acc[1][3], a1, b1 + 2);
    }
}

// ---------------- K1: setup + all-layer prep (launch #1) ----------------
__global__ void k1_setup(const float* __restrict__ Lam, const float* __restrict__ pw1,
                         const float* __restrict__ pb1, const float* __restrict__ pw2,
                         const float* __restrict__ pb2,
                         const float* __restrict__ enc_w, const float* __restrict__ enc_b,
                         const float* __restrict__ lin_w, const float* __restrict__ lin_b) {
    int bid = blockIdx.x, t = threadIdx.x;
    size_t i = (size_t)bid * 256 + t;
    ((float4*)g_agg)[i] = make_float4(0.f, 0.f, 0.f, 0.f);
    if (i < SLOTMAX) g_ssrc[i] = -1;
    if (bid == 0) {
        g_stats[t] = 0.f;
        if (t < 128) g_gcnt[t] = 0;
        if (t == 0) g_flag = 0;
    }
    if (bid >= 4000 && bid < 4256 && t < 64) {
        int idx = bid - 4000;
        int l = idx >> 6, k = idx & 63, hh = t;
        const float* ew = enc_w + (size_t)l * 4096;
        const float* lw = lin_w + (size_t)l * 4096;
        float s = 0.f;
        for (int j = 0; j < 64; j++) s += ew[k * 64 + j] * lw[j * 64 + hh];
        g_Wc4[l * 8192 + k * 64 + hh] = s;
        g_Wc4[l * 8192 + (64 + k) * 64 + hh] = lw[k * 64 + hh];
        if (k == 0) {
            float bias = lin_b[l * 64 + hh];
            for (int j = 0; j < 64; j++) bias += enc_b[l * 64 + j] * lw[j * 64 + hh];
            g_bc4[l * 64 + hh] = bias;
        }
    }
    if (bid >= 4300 && bid < 4350) {
        int idx = (bid - 4300) * 256 + t;   // < 12800
        int l = idx / 3200, j = idx % 3200;
        float lam = Lam[j];
        float s = pb2[l];
#pragma unroll
        for (int jj = 0; jj < 16; jj++) {
            float h = fmaxf(lam * pw1[l * 16 + jj] + pb1[l * 16 + jj], 0.f);
            s += h * pw2[l * 16 + jj];
        }
        g_wtab4[idx] = s;
    }
}

// ---------------- K2: count + all-layer weight bf16 prep (launch #2) ----------------
__global__ void k2_count_wprep(const int* __restrict__ ei, const int* __restrict__ batch) {
    int bid = blockIdx.x, t = threadIdx.x;
    if (bid < 3125) {
        int e = bid * 256 + t;
        if (e < EE) atomicAdd(&g_gcnt[batch[ei[e]]], 1);
        return;
    }
    int idx = bid - 3125;          // 0..403
    int l = idx / 101, sub = idx % 101;
    if (sub < BB) {
        size_t base = ((size_t)l * BB + sub) * 4096;
#pragma unroll 4
        for (int i = 0; i < 16; i++) {
            int p = i * 256 + t;
            int c = p >> 6, k = p & 63;
            float w = g_wtab4[l * 3200 + sub * 32 + (k & 31)] * g_Wc4[l * 8192 + k * 64 + c];
            __nv_bfloat16 h = __float2bfloat16(w);
            g_B1h4[base + p] = h;
            g_B1l4[base + p] = __float2bfloat16(w - __bfloat162float(h));
        }
    } else {
#pragma unroll 4
        for (int i = 0; i < 16; i++) {
            int p = i * 256 + t;
            int c = p >> 6, k = p & 63;
            float w = g_Wc4[l * 8192 + (64 + k) * 64 + c];
            __nv_bfloat16 h = __float2bfloat16(w);
            g_B2h4[l * 4096 + p] = h;
            g_B2l4[l * 4096 + p] = __float2bfloat16(w - __bfloat162float(h));
        }
    }
}

// ---------------- K3: scan (block 0) + fill + convert (launch #3) ----------------
__global__ __launch_bounds__(256) void k3_scan_fill_convert(const float* __restrict__ pe,
                                                            const float* __restrict__ edge_attr,
                                                            const int* __restrict__ ei,
                                                            const int* __restrict__ batch) {
    __shared__ int sNT[128];
    __shared__ int sTot;
    int t = threadIdx.x;
    if (blockIdx.x == 0) {
        int nt = 0;
        if (t < 128) {
            int cnt = (t < BB) ? g_gcnt[t] : 0;
            nt = (cnt + 127) >> 7;
            sNT[t] = nt;
        }
        __syncthreads();
        for (int off = 1; off < 128; off <<= 1) {
            int v = (t >= off && t < 128) ? sNT[t - off] : 0;
            __syncthreads();
            if (t < 128) sNT[t] += v;
            __syncthreads();
        }
        if (t < BB) {
            int excl = sNT[t] - nt;
            g_gcur[t] = excl * 128;
            for (int j = 0; j < nt; j++) g_tile_g[excl + j] = t;
        }
        if (t == 127) sTot = sNT[127];
        __syncthreads();
        for (int i = sTot + t; i < MAXT; i += 256) g_tile_g[i] = -1;
        __threadfence();
        __syncthreads();
        if (t == 0) atomicExch(&g_flag, 1);
    } else {
        if (t == 0) {
            while (atomicAdd(&g_flag, 0) == 0) __nanosleep(64);
        }
        __syncthreads();
    }

    int e = blockIdx.x * 8 + (t >> 5);
    int qm = t & 31;
    int src = ei[e];
    int dst = ei[EE + e];
    int slot = 0;
    if (qm == 0) slot = atomicAdd(&g_gcur[batch[src]], 1);
    slot = __shfl_sync(0xffffffffu, slot, 0);

    const float2* pe2 = (const float2*)pe;
    float2 zs = pe2[(size_t)src * 32 + qm];
    float2 zd = pe2[(size_t)dst * 32 + qm];
    float zr = zs.x * zd.x + zs.y * zd.y;
    float zi = zs.y * zd.x - zs.x * zd.y;
    size_t base = (size_t)slot * 64;
    __nv_bfloat16 h;
    h = __float2bfloat16(zr); g_A1h[base + qm] = h;
    g_A1l[base + qm] = __float2bfloat16(zr - __bfloat162float(h));
    h = __float2bfloat16(zi); g_A1h[base + 32 + qm] = h;
    g_A1l[base + 32 + qm] = __float2bfloat16(zi - __bfloat162float(h));
    float a0 = edge_attr[(size_t)e * 64 + qm];
    float a1 = edge_attr[(size_t)e * 64 + 32 + qm];
    h = __float2bfloat16(a0); g_A2h[base + qm] = h;
    g_A2l[base + qm] = __float2bfloat16(a0 - __bfloat162float(h));
    h = __float2bfloat16(a1); g_A2h[base + 32 + qm] = h;
    g_A2l[base + 32 + qm] = __float2bfloat16(a1 - __bfloat162float(h));
    if (qm == 0) { g_ssrc[slot] = src; g_sdst[slot] = dst; }
}

// ---------------- edge kernel: each matrix staged exactly once ----------------
// products: A1h*B1h, A1h*B1l, A1l*B1h, A2h*B2h, A2h*B2l, A2l*B2h
__global__ __launch_bounds__(256, 3) void edge_mma_kernel(const float* __restrict__ xsrc,
                                                          int l, int use_bn) {
    extern __shared__ char sm[];
    uint32_t sb = smem_u32(sm);
    int t = threadIdx.x;
    int lane = t & 31, w = t >> 5;
    if (blockIdx.x == 0) g_stats[t] = 0.f;
    int tile = blockIdx.x;
    int b = g_tile_g[tile];
    if (b < 0) return;

    size_t bbase = ((size_t)l * BB + b) * 4096;
    const char* A1hp = (const char*)(g_A1h + (size_t)tile * 8192);
    const char* A1lp = (const char*)(g_A1l + (size_t)tile * 8192);
    const char* A2hp = (const char*)(g_A2h + (size_t)tile * 8192);
    const char* A2lp = (const char*)(g_A2l + (size_t)tile * 8192);
    const char* B1hp = (const char*)(g_B1h4 + bbase);
    const char* B1lp = (const char*)(g_B1l4 + bbase);
    const char* B2hp = (const char*)(g_B2h4 + l * 4096);
    const char* B2lp = (const char*)(g_B2l4 + l * 4096);

#define STAGE_A(G, OFF) { \
    _Pragma("unroll") \
    for (int i = 0; i < 4; i++) { \
        int lin = i * 256 + t; \
        cp16(sb + (OFF) + (lin >> 3) * 144 + (lin & 7) * 16, (G) + lin * 16); } }
#define STAGE_B(G, OFF) { \
    _Pragma("unroll") \
    for (int i = 0; i < 2; i++) { \
        int lin = i * 256 + t; \
        cp16(sb + (OFF) + (lin >> 3) * 144 + (lin & 7) * 16, (G) + lin * 16); } }

    STAGE_A(A1hp, OA0); STAGE_B(B1hp, OB0); cp_commit();   // G0
    STAGE_B(B1lp, OB1); cp_commit();                        // G1
    STAGE_A(A1lp, OA1); cp_commit();                        // G2

    uint32_t aOff = (uint32_t)((w & 3) * 32 + (lane & 15)) * 144 + ((lane >> 4) & 1) * 16;
    uint32_t bOff = (uint32_t)((w >> 2) * 32 + ((lane >> 4) & 1) * 8 + (lane & 7)) * 144
                  + ((lane >> 3) & 1) * 16;

    float acc[2][4][4];
#pragma unroll
    for (int mt = 0; mt < 2; mt++)
#pragma unroll
        for (int nt = 0; nt < 4; nt++)
#pragma unroll
            for (int j = 0; j < 4; j++) acc[mt][nt][j] = 0.f;

    // p0: A1h (A0) * B1h (B0)
    asm volatile("cp.async.wait_group 2;" ::: "memory"); __syncthreads();
    product(acc, sb + OA0 + aOff, sb + OB0 + bOff);
    // p1: A1h (A0) * B1l (B1)
    asm volatile("cp.async.wait_group 1;" ::: "memory"); __syncthreads();
    product(acc, sb + OA0 + aOff, sb + OB1 + bOff);
    __syncthreads();                         // WAR: A0 free
    STAGE_A(A2hp, OA0); cp_commit();         // G3
    // p2: A1l (A1) * B1h (B0)   [needs G2; pending after wait: G3]
    asm volatile("cp.async.wait_group 1;" ::: "memory"); __syncthreads();
    product(acc, sb + OA1 + aOff, sb + OB0 + bOff);
    __syncthreads();                         // WAR: B0, A1 free
    STAGE_B(B2hp, OB0); cp_commit();         // G4
    STAGE_B(B2lp, OB1); STAGE_A(A2lp, OA1); cp_commit();   // G5
    // p3: A2h (A0) * B2h (B0)   [needs G3,G4; pending after wait: G5]
    asm volatile("cp.async.wait_group 1;" ::: "memory"); __syncthreads();
    product(acc, sb + OA0 + aOff, sb + OB0 + bOff);
    // p4/p5 need G5
    asm volatile("cp.async.wait_group 0;" ::: "memory"); __syncthreads();
    product(acc, sb + OA0 + aOff, sb + OB1 + bOff);   // A2h * B2l
    product(acc, sb + OA1 + aOff, sb + OB0 + bOff);   // A2l * B2h
    __syncthreads();   // A region dead; overlay D

    // ---- write D frags (row stride 272B) ----
    int wm = w & 3, wn = w >> 2;
    int g = lane >> 2, tig = lane & 3;
#pragma unroll
    for (int mt = 0; mt < 2; mt++) {
        int r0 = wm * 32 + mt * 16 + g;
#pragma unroll
        for (int nt = 0; nt < 4; nt++) {
            int c = wn * 32 + nt * 8 + tig * 2;
            *(float2*)(sm + OD + r0 * 272 + c * 4) = make_float2(acc[mt][nt][0], acc[mt][nt][1]);
            *(float2*)(sm + OD + (r0 + 8) * 272 + c * 4) = make_float2(acc[mt][nt][2], acc[mt][nt][3]);
        }
    }
    __syncthreads();

    // ---- epilogue: 2 threads per edge; fused BN on x gather ----
    int edge = t >> 1, half = t & 1;
    int slot = tile * 128 + edge;
    int srcn = g_ssrc[slot];
    if (srcn >= 0) {
        int dstn = g_sdst[slot];
        const float* Dr = (const float*)(sm + OD + edge * 272 + half * 128);
        const float* xr = xsrc + (size_t)srcn * 64 + half * 32;
        const float* br = g_bc4 + l * 64 + half * 32;
        const float* scp = g_bnsc + half * 32;
        const float* shp = g_bnsh + half * 32;
        float* dp = g_agg + (size_t)dstn * 64 + half * 32;
#pragma unroll
        for (int q = 0; q < 8; q++) {
            float4 dv = *(const float4*)(Dr + q * 4);
            float4 xv = *(const float4*)(xr + q * 4);
            if (use_bn) {
                float4 sc = *(const float4*)(scp + q * 4);
                float4 sh = *(const float4*)(shp + q * 4);
                xv.x = fmaxf(xv.x * sc.x + sh.x, 0.f);
                xv.y = fmaxf(xv.y * sc.y + sh.y, 0.f);
                xv.z = fmaxf(xv.z * sc.z + sh.z, 0.f);
                xv.w = fmaxf(xv.w * sc.w + sh.w, 0.f);
            }
            float4 bc = *(const float4*)(br + q * 4);
            red_add_v4(dp + q * 4,
                       fmaxf(dv.x + bc.x + xv.x, 0.f), fmaxf(dv.y + bc.y + xv.y, 0.f),
                       fmaxf(dv.z + bc.z + xv.z, 0.f), fmaxf(dv.w + bc.w + xv.w, 0.f));
        }
    }
}

// ---------------- node kernels ----------------
__global__ __launch_bounds__(256) void nodeA_kernel(const float* __restrict__ xsrc,
                                                    const float* __restrict__ W,
                                                    const float* __restrict__ bias,
                                                    int l, int use_bn) {
    __shared__ float sW[64 * 64];
    __shared__ float sA[64 * 32];
    __shared__ float sRs[256], sRq[256];
    int t = threadIdx.x;
    int n0 = blockIdx.x * 32;
    {
        const float4* Wv = (const float4*)(W + (size_t)l * 4096);
        float4* sWv = (float4*)sW;
#pragma unroll
        for (int i = 0; i < 4; i++) sWv[t + 256 * i] = Wv[t + 256 * i];
    }
    int n_loc = t & 31, part = t >> 5;
    int k0 = part * 8;
    {
        size_t base = (size_t)(n0 + n_loc) * 64 + k0;
        float4 x0 = *(const float4*)(xsrc + base);
        float4 x1 = *(const float4*)(xsrc + base + 4);
        if (use_bn) {
            float4 sc0 = *(const float4*)(g_bnsc + k0);
            float4 sc1 = *(const float4*)(g_bnsc + k0 + 4);
            float4 sh0 = *(const float4*)(g_bnsh + k0);
            float4 sh1 = *(const float4*)(g_bnsh + k0 + 4);
            x0.x = fmaxf(x0.x * sc0.x + sh0.x, 0.f);
            x0.y = fmaxf(x0.y * sc0.y + sh0.y, 0.f);
            x0.z = fmaxf(x0.z * sc0.z + sh0.z, 0.f);
            x0.w = fmaxf(x0.w * sc0.w + sh0.w, 0.f);
            x1.x = fmaxf(x1.x * sc1.x + sh1.x, 0.f);
            x1.y = fmaxf(x1.y * sc1.y + sh1.y, 0.f);
            x1.z = fmaxf(x1.z * sc1.z + sh1.z, 0.f);
            x1.w = fmaxf(x1.w * sc1.w + sh1.w, 0.f);
        }
        float4 a0 = *(const float4*)(g_agg + base);
        float4 a1 = *(const float4*)(g_agg + base + 4);
        *(float4*)(g_agg + base) = make_float4(0.f, 0.f, 0.f, 0.f);
        *(float4*)(g_agg + base + 4) = make_float4(0.f, 0.f, 0.f, 0.f);
        sA[(k0 + 0) * 32 + n_loc] = x0.x + a0.x;
        sA[(k0 + 1) * 32 + n_loc] = x0.y + a0.y;
        sA[(k0 + 2) * 32 + n_loc] = x0.z + a0.z;
        sA[(k0 + 3) * 32 + n_loc] = x0.w + a0.w;
        sA[(k0 + 4) * 32 + n_loc] = x1.x + a1.x;
        sA[(k0 + 5) * 32 + n_loc] = x1.y + a1.y;
        sA[(k0 + 6) * 32 + n_loc] = x1.z + a1.z;
        sA[(k0 + 7) * 32 + n_loc] = x1.w + a1.w;
    }
    __syncthreads();

    int tx = t & 63, ty = t >> 6;
    unsigned long long acc[4] = {0ull, 0ull, 0ull, 0ull};
#pragma unroll 8
    for (int k = 0; k < 64; k++) {
        float w = sW[k * 64 + tx];
        unsigned long long w2 = pack2(w, w);
        const ulonglong2* ap = (const ulonglong2*)(sA + k * 32 + ty * 8);
        ulonglong2 a01 = ap[0];
        ulonglong2 a23 = ap[1];
        ffma2(acc[0], a01.x, w2);
        ffma2(acc[1], a01.y, w2);
        ffma2(acc[2], a23.x, w2);
        ffma2(acc[3], a23.y, w2);
    }
    float bb = bias[l * 64 + tx];
    float s = 0.f, q = 0.f;
#pragma unroll
    for (int p = 0; p < 4; p++) {
        float2 v = unpack2(acc[p]);
        int na = ty * 8 + p * 2;
        float yA = v.x + bb, yB = v.y + bb;
        g_y1[(size_t)(n0 + na) * 64 + tx] = yA;
        g_y1[(size_t)(n0 + na + 1) * 64 + tx] = yB;
        s += yA + yB;
        q += yA * yA + yB * yB;
    }
    sRs[t] = s;
    sRq[t] = q;
    __syncthreads();
    if (t < 64) {
        s = sRs[t] + sRs[64 + t] + sRs[128 + t] + sRs[192 + t];
        q = sRq[t] + sRq[64 + t] + sRq[128 + t] + sRq[192 + t];
        atomicAdd(&g_stats[t], s);
        atomicAdd(&g_stats[64 + t], q);
    }
}

__global__ __launch_bounds__(256) void nodeB_kernel(const float* __restrict__ W,
                                                    const float* __restrict__ bias,
                                                    const float* __restrict__ bg,
                                                    const float* __restrict__ bnb, int l) {
    __shared__ float sW[64 * 64];
    __shared__ float sA[64 * 32];
    __shared__ float sSc[64], sSh[64];
    __shared__ float sRs[256], sRq[256];
    int t = threadIdx.x;
    int n0 = blockIdx.x * 32;
    {
        const float4* Wv = (const float4*)(W + (size_t)l * 4096);
        float4* sWv = (float4*)sW;
#pragma unroll
        for (int i = 0; i < 4; i++) sWv[t + 256 * i] = Wv[t + 256 * i];
    }
    if (t < 64) {
        float mu = g_stats[t] * (1.0f / NN);
        float var = g_stats[64 + t] * (1.0f / NN) - mu * mu;
        float rs = rsqrtf(var + EPS_BN);
        float sc = rs * bg[l * 64 + t];
        sSc[t] = sc;
        sSh[t] = bnb[l * 64 + t] - mu * sc;
    }
    __syncthreads();
    int n_loc = t & 31, part = t >> 5;
    int k0 = part * 8;
    {
        size_t base = (size_t)(n0 + n_loc) * 64 + k0;
        float4 y0 = *(const float4*)(g_y1 + base);
        float4 y1v = *(const float4*)(g_y1 + base + 4);
        sA[(k0 + 0) * 32 + n_loc] = fmaxf(y0.x * sSc[k0 + 0] + sSh[k0 + 0], 0.f);
        sA[(k0 + 1) * 32 + n_loc] = fmaxf(y0.y * sSc[k0 + 1] + sSh[k0 + 1], 0.f);
        sA[(k0 + 2) * 32 + n_loc] = fmaxf(y0.z * sSc[k0 + 2] + sSh[k0 + 2], 0.f);
        sA[(k0 + 3) * 32 + n_loc] = fmaxf(y0.w * sSc[k0 + 3] + sSh[k0 + 3], 0.f);
        sA[(k0 + 4) * 32 + n_loc] = fmaxf(y1v.x * sSc[k0 + 4] + sSh[k0 + 4], 0.f);
        sA[(k0 + 5) * 32 + n_loc] = fmaxf(y1v.y * sSc[k0 + 5] + sSh[k0 + 5], 0.f);
        sA[(k0 + 6) * 32 + n_loc] = fmaxf(y1v.z * sSc[k0 + 6] + sSh[k0 + 6], 0.f);
        sA[(k0 + 7) * 32 + n_loc] = fmaxf(y1v.w * sSc[k0 + 7] + sSh[k0 + 7], 0.f);
    }
    __syncthreads();

    int tx = t & 63, ty = t >> 6;
    unsigned long long acc[4] = {0ull, 0ull, 0ull, 0ull};
#pragma unroll 8
    for (int k = 0; k < 64; k++) {
        float w = sW[k * 64 + tx];
        unsigned long long w2 = pack2(w, w);
        const ulonglong2* ap = (const ulonglong2*)(sA + k * 32 + ty * 8);
        ulonglong2 a01 = ap[0];
        ulonglong2 a23 = ap[1];
        ffma2(acc[0], a01.x, w2);
        ffma2(acc[1], a01.y, w2);
        ffma2(acc[2], a23.x, w2);
        ffma2(acc[3], a23.y, w2);
    }
    float bb = bias[l * 64 + tx];
    float s = 0.f, q = 0.f;
#pragma unroll
    for (int p = 0; p < 4; p++) {
        float2 v = unpack2(acc[p]);
        int na = ty * 8 + p * 2;
        float yA = v.x + bb, yB = v.y + bb;
        g_y2[(size_t)(n0 + na) * 64 + tx] = yA;
        g_y2[(size_t)(n0 + na + 1) * 64 + tx] = yB;
        s += yA + yB;
        q += yA * yA + yB * yB;
    }
    sRs[t] = s;
    sRq[t] = q;
    __syncthreads();
    if (t < 64) {
        s = sRs[t] + sRs[64 + t] + sRs[128 + t] + sRs[192 + t];
        q = sRq[t] + sRq[64 + t] + sRq[128 + t] + sRq[192 + t];
        atomicAdd(&g_stats[128 + t], s);
        atomicAdd(&g_stats[192 + t], q);
    }
}

// tiny: derive sc/sh from BN2 stats for fused application next layer
__global__ void bnsc_kernel(const float* __restrict__ bg, const float* __restrict__ bnb, int l) {
    int t = threadIdx.x;   // 64
    float mu = g_stats[128 + t] * (1.0f / NN);
    float var = g_stats[192 + t] * (1.0f / NN) - mu * mu;
    float rs = rsqrtf(var + EPS_BN);
    float sc = rs * bg[l * 64 + t];
    g_bnsc[t] = sc;
    g_bnsh[t] = bnb[l * 64 + t] - mu * sc;
}

// final-layer BN2 apply (no relu) writing the output
__global__ void bn_apply_kernel(const float* __restrict__ bg, const float* __restrict__ bnb,
                                float* __restrict__ xout, int l) {
    int i = blockIdx.x * 256 + threadIdx.x;
    int h = i & 63;
    float mu = g_stats[128 + h] * (1.0f / NN);
    float var = g_stats[192 + h] * (1.0f / NN) - mu * mu;
    float rs = rsqrtf(var + EPS_BN);
    float sc = rs * bg[l * 64 + h];
    float sh = bnb[l * 64 + h] - mu * sc;
    xout[i] = g_y2[i] * sc + sh;
}

__global__ void copy_pe_kernel(const float* __restrict__ pe, float* __restrict__ out) {
    size_t i = (size_t)blockIdx.x * 256 + threadIdx.x;
    ((float4*)out)[i] = ((const float4*)pe)[i];
}

// ---------------- launcher ----------------
extern "C" void kernel_launch(void* const* d_in, const int* in_sizes, int n_in,
                              void* d_out, int out_size) {
    const float* x        = (const float*)d_in[0];
    const float* pe       = (const float*)d_in[1];
    const float* Lam      = (const float*)d_in[2];
    const float* edge_attr= (const float*)d_in[3];
    const float* pw1      = (const float*)d_in[4];
    const float* pb1      = (const float*)d_in[5];
    const float* pw2      = (const float*)d_in[6];
    const float* pb2      = (const float*)d_in[7];
    const float* enc_w    = (const float*)d_in[8];
    const float* enc_b    = (const float*)d_in[9];
    const float* lin_w    = (const float*)d_in[10];
    const float* lin_b    = (const float*)d_in[11];
    const float* mw1      = (const float*)d_in[12];
    const float* mb1      = (const float*)d_in[13];
    const float* bn1g     = (const float*)d_in[14];
    const float* bn1b     = (const float*)d_in[15];
    const float* mw2      = (const float*)d_in[16];
    const float* mb2      = (const float*)d_in[17];
    const float* bn2g     = (const float*)d_in[18];
    const float* bn2b     = (const float*)d_in[19];
    const int*   ei       = (const int*)d_in[20];
    const int*   batch    = (const int*)d_in[21];
    float* out = (float*)d_out;

    float* y2 = nullptr;
    cudaGetSymbolAddress((void**)&y2, g_y2);
    cudaFuncSetAttribute(edge_mma_kernel, cudaFuncAttributeMaxDynamicSharedMemorySize, SMEM_EDGE);

    k1_setup<<<6250, 256>>>(Lam, pw1, pb1, pw2, pb2, enc_w, enc_b, lin_w, lin_b);
    k2_count_wprep<<<3125 + 404, 256>>>(ei, batch);
    k3_scan_fill_convert<<<EE / 8, 256>>>(pe, edge_attr, ei, batch);

    for (int l = 0; l < LL; l++) {
        const float* xsrc = (l == 0) ? x : (const float*)y2;
        int use_bn = (l != 0);
        edge_mma_kernel<<<MAXT, 256, SMEM_EDGE>>>(xsrc, l, use_bn);
        nodeA_kernel<<<NN / 32, 256>>>(xsrc, mw1, mb1, l, use_bn);
        nodeB_kernel<<<NN / 32, 256>>>(mw2, mb2, bn1g, bn1b, l);
        if (l != LL - 1) {
            bnsc_kernel<<<1, 64>>>(bn2g, bn2b, l);
        } else {
            bn_apply_kernel<<<NN * 64 / 256, 256>>>(bn2g, bn2b, out, l);
        }
    }
    if (out_size >= (int)(2u * NN * 64)) {
        copy_pe_kernel<<<NN * 16 / 256, 256>>>(pe, out + (size_t)NN * 64);
    }
}

// round 16
// speedup vs baseline: 1.1601x; 1.1427x over previous
#include <cuda_runtime.h>
#include <cuda_bf16.h>
#include <cstdint>

#define NN 100000
#define EE 800000
#define QMM 32
#define BB 100
#define LL 4
#define EPS_BN 1e-5f
#define SLOTMAX 812800          // >= EE + 127*BB
#define MAXT 6350               // SLOTMAX / 128

// edge kernel smem: A0,A1 (18432 each) + B0,B1 (9216 each) = 55296 bytes
#define OA0 0
#define OA1 18432
#define OB0 36864
#define OB1 46080
#define SMEM_EDGE 55296
#define OD 0                    // D overlay (128 x 272B = 34816B) over dead A bufs

// ---------------- scratch ----------------
__device__ __nv_bfloat16 g_A1h[(size_t)SLOTMAX * 64];
__device__ __nv_bfloat16 g_A1l[(size_t)SLOTMAX * 64];
__device__ __nv_bfloat16 g_A2h[(size_t)SLOTMAX * 64];
__device__ __nv_bfloat16 g_A2l[(size_t)SLOTMAX * 64];
__device__ __nv_bfloat16 g_B1h4[(size_t)LL * BB * 4096];   // per-layer per-graph W1b hi
__device__ __nv_bfloat16 g_B1l4[(size_t)LL * BB * 4096];
__device__ __nv_bfloat16 g_B2h4[LL * 4096];
__device__ __nv_bfloat16 g_B2l4[LL * 4096];
__device__ int   g_ssrc[SLOTMAX];
__device__ int   g_sdst[SLOTMAX];
__device__ int   g_gcnt[128], g_gcur[128];
__device__ int   g_tile_g[MAXT];
__device__ int   g_flag;
__device__ float g_agg[(size_t)NN * 64];
__device__ float g_y1[(size_t)NN * 64];
__device__ float g_y2[(size_t)NN * 64];
__device__ float g_xb[(size_t)NN * 64];     // BN2-applied node features
__device__ float g_wtab4[LL * BB * QMM];
__device__ float g_Wc4[LL * 128 * 64];
__device__ float g_bc4[LL * 64];
__device__ float g_stats[256];

// ---------------- helpers ----------------
__device__ __forceinline__ unsigned long long pack2(float a, float b) {
    unsigned long long r;
    asm("mov.b64 %0, {%1, %2};" : "=l"(r) : "f"(a), "f"(b));
    return r;
}
__device__ __forceinline__ void ffma2(unsigned long long& d, unsigned long long a, unsigned long long b) {
    asm("fma.rn.f32x2 %0, %1, %2, %0;" : "+l"(d) : "l"(a), "l"(b));
}
__device__ __forceinline__ float2 unpack2(unsigned long long v) {
    float2 r;
    asm("mov.b64 {%0, %1}, %2;" : "=f"(r.x), "=f"(r.y) : "l"(v));
    return r;
}
__device__ __forceinline__ void red_add_v4(float* p, float a, float b, float c, float d) {
    asm volatile("red.global.add.v4.f32 [%0], {%1, %2, %3, %4};"
                 :: "l"(p), "f"(a), "f"(b), "f"(c), "f"(d) : "memory");
}
__device__ __forceinline__ void mma16816(float* c, const uint32_t* a, const uint32_t* b) {
    asm volatile(
        "mma.sync.aligned.m16n8k16.row.col.f32.bf16.bf16.f32 "
        "{%0,%1,%2,%3}, {%4,%5,%6,%7}, {%8,%9}, {%0,%1,%2,%3};"
        : "+f"(c[0]), "+f"(c[1]), "+f"(c[2]), "+f"(c[3])
        : "r"(a[0]), "r"(a[1]), "r"(a[2]), "r"(a[3]), "r"(b[0]), "r"(b[1]));
}
__device__ __forceinline__ uint32_t smem_u32(const void* p) {
    uint32_t a;
    asm("{ .reg .u64 t; cvta.to.shared.u64 t, %1; cvt.u32.u64 %0, t; }" : "=r"(a) : "l"(p));
    return a;
}
__device__ __forceinline__ void ldsm4(uint32_t* r, uint32_t a) {
    asm volatile("ldmatrix.sync.aligned.m8n8.x4.shared.b16 {%0,%1,%2,%3}, [%4];"
                 : "=r"(r[0]), "=r"(r[1]), "=r"(r[2]), "=r"(r[3]) : "r"(a));
}
__device__ __forceinline__ void cp16(uint32_t d, const void* s) {
    asm volatile("cp.async.cg.shared.global [%0], [%1], 16;" :: "r"(d), "l"(s) : "memory");
}
__device__ __forceinline__ void cp_commit() { asm volatile("cp.async.commit_group;" ::: "memory"); }

__device__ __forceinline__ void product(float (&acc)[2][4][4], uint32_t aB, uint32_t bB) {
#pragma unroll
    for (int kc = 0; kc < 4; kc++) {
        uint32_t a0[4], a1[4], b0[4], b1[4];
        ldsm4(a0, aB + kc * 32);
        ldsm4(a1, aB + 16 * 144 + kc * 32);
        ldsm4(b0, bB + kc * 32);
        ldsm4(b1, bB + 16 * 144 + kc * 32);
        mma16816(acc[0][0], a0, b0);
        mma16816(acc[0][1], a0, b0 + 2);
        mma16816(acc[0][2], a0, b1);
        mma16816(acc[0][3], a0, b1 + 2);
        mma16816(acc[1][0], a1, b0);
        mma16816(acc[1][1], a1, b0 + 2);
        mma16816(acc[1][2], a1, b1);
        mma16816(acc[1][3], a1, b1 + 2);
    }
}

// ---------------- K1: setup + all-layer prep (launch #1) ----------------
__global__ void k1_setup(const float* __restrict__ Lam, const float* __restrict__ pw1,
                         const float* __restrict__ pb1, const float* __restrict__ pw2,
                         const float* __restrict__ pb2,
                         const float* __restrict__ enc_w, const float* __restrict__ enc_b,
                         const float* __restrict__ lin_w, const float* __restrict__ lin_b) {
    int bid = blockIdx.x, t = threadIdx.x;
    size_t i = (size_t)bid * 256 + t;
    ((float4*)g_agg)[i] = make_float4(0.f, 0.f, 0.f, 0.f);
    if (i < SLOTMAX) g_ssrc[i] = -1;
    if (bid == 0) {
        g_stats[t] = 0.f;
        if (t < 128) g_gcnt[t] = 0;
        if (t == 0) g_flag = 0;
    }
    if (bid >= 4000 && bid < 4256 && t < 64) {
        int idx = bid - 4000;
        int l = idx >> 6, k = idx & 63, hh = t;
        const float* ew = enc_w + (size_t)l * 4096;
        const float* lw = lin_w + (size_t)l * 4096;
        float s = 0.f;
        for (int j = 0; j < 64; j++) s += ew[k * 64 + j] * lw[j * 64 + hh];
        g_Wc4[l * 8192 + k * 64 + hh] = s;
        g_Wc4[l * 8192 + (64 + k) * 64 + hh] = lw[k * 64 + hh];
        if (k == 0) {
            float bias = lin_b[l * 64 + hh];
            for (int j = 0; j < 64; j++) bias += enc_b[l * 64 + j] * lw[j * 64 + hh];
            g_bc4[l * 64 + hh] = bias;
        }
    }
    if (bid >= 4300 && bid < 4350) {
        int idx = (bid - 4300) * 256 + t;   // < 12800
        int l = idx / 3200, j = idx % 3200;
        float lam = Lam[j];
        float s = pb2[l];
#pragma unroll
        for (int jj = 0; jj < 16; jj++) {
            float h = fmaxf(lam * pw1[l * 16 + jj] + pb1[l * 16 + jj], 0.f);
            s += h * pw2[l * 16 + jj];
        }
        g_wtab4[idx] = s;
    }
}

// ---------------- K2: count + all-layer weight bf16 prep (launch #2) ----------------
__global__ void k2_count_wprep(const int* __restrict__ ei, const int* __restrict__ batch) {
    int bid = blockIdx.x, t = threadIdx.x;
    if (bid < 3125) {
        int e = bid * 256 + t;
        if (e < EE) atomicAdd(&g_gcnt[batch[ei[e]]], 1);
        return;
    }
    int idx = bid - 3125;          // 0..403
    int l = idx / 101, sub = idx % 101;
    if (sub < BB) {
        size_t base = ((size_t)l * BB + sub) * 4096;
#pragma unroll 4
        for (int i = 0; i < 16; i++) {
            int p = i * 256 + t;
            int c = p >> 6, k = p & 63;
            float w = g_wtab4[l * 3200 + sub * 32 + (k & 31)] * g_Wc4[l * 8192 + k * 64 + c];
            __nv_bfloat16 h = __float2bfloat16(w);
            g_B1h4[base + p] = h;
            g_B1l4[base + p] = __float2bfloat16(w - __bfloat162float(h));
        }
    } else {
#pragma unroll 4
        for (int i = 0; i < 16; i++) {
            int p = i * 256 + t;
            int c = p >> 6, k = p & 63;
            float w = g_Wc4[l * 8192 + (64 + k) * 64 + c];
            __nv_bfloat16 h = __float2bfloat16(w);
            g_B2h4[l * 4096 + p] = h;
            g_B2l4[l * 4096 + p] = __float2bfloat16(w - __bfloat162float(h));
        }
    }
}

// ---------------- K3: scan (block 0) + fill + convert (launch #3) ----------------
__global__ __launch_bounds__(256) void k3_scan_fill_convert(const float* __restrict__ pe,
                                                            const float* __restrict__ edge_attr,
                                                            const int* __restrict__ ei,
                                                            const int* __restrict__ batch) {
    __shared__ int sNT[128];
    __shared__ int sTot;
    int t = threadIdx.x;
    if (blockIdx.x == 0) {
        int nt = 0;
        if (t < 128) {
            int cnt = (t < BB) ? g_gcnt[t] : 0;
            nt = (cnt + 127) >> 7;
            sNT[t] = nt;
        }
        __syncthreads();
        for (int off = 1; off < 128; off <<= 1) {
            int v = (t >= off && t < 128) ? sNT[t - off] : 0;
            __syncthreads();
            if (t < 128) sNT[t] += v;
            __syncthreads();
        }
        if (t < BB) {
            int excl = sNT[t] - nt;
            g_gcur[t] = excl * 128;
            for (int j = 0; j < nt; j++) g_tile_g[excl + j] = t;
        }
        if (t == 127) sTot = sNT[127];
        __syncthreads();
        for (int i = sTot + t; i < MAXT; i += 256) g_tile_g[i] = -1;
        __threadfence();
        __syncthreads();
        if (t == 0) atomicExch(&g_flag, 1);
    } else {
        if (t == 0) {
            while (atomicAdd(&g_flag, 0) == 0) __nanosleep(64);
        }
        __syncthreads();
    }

    int e = blockIdx.x * 8 + (t >> 5);
    int qm = t & 31;
    int src = ei[e];
    int dst = ei[EE + e];
    int slot = 0;
    if (qm == 0) slot = atomicAdd(&g_gcur[batch[src]], 1);
    slot = __shfl_sync(0xffffffffu, slot, 0);

    const float2* pe2 = (const float2*)pe;
    float2 zs = pe2[(size_t)src * 32 + qm];
    float2 zd = pe2[(size_t)dst * 32 + qm];
    float zr = zs.x * zd.x + zs.y * zd.y;
    float zi = zs.y * zd.x - zs.x * zd.y;
    size_t base = (size_t)slot * 64;
    __nv_bfloat16 h;
    h = __float2bfloat16(zr); g_A1h[base + qm] = h;
    g_A1l[base + qm] = __float2bfloat16(zr - __bfloat162float(h));
    h = __float2bfloat16(zi); g_A1h[base + 32 + qm] = h;
    g_A1l[base + 32 + qm] = __float2bfloat16(zi - __bfloat162float(h));
    float a0 = edge_attr[(size_t)e * 64 + qm];
    float a1 = edge_attr[(size_t)e * 64 + 32 + qm];
    h = __float2bfloat16(a0); g_A2h[base + qm] = h;
    g_A2l[base + qm] = __float2bfloat16(a0 - __bfloat162float(h));
    h = __float2bfloat16(a1); g_A2h[base + 32 + qm] = h;
    g_A2l[base + 32 + qm] = __float2bfloat16(a1 - __bfloat162float(h));
    if (qm == 0) { g_ssrc[slot] = src; g_sdst[slot] = dst; }
}

// ---------------- edge kernel: each matrix staged exactly once ----------------
// products: A1h*B1h, A1h*B1l, A1l*B1h, A2h*B2h, A2h*B2l, A2l*B2h
__global__ __launch_bounds__(256, 3) void edge_mma_kernel(const float* __restrict__ xcur, int l) {
    extern __shared__ char sm[];
    uint32_t sb = smem_u32(sm);
    int t = threadIdx.x;
    int lane = t & 31, w = t >> 5;
    if (blockIdx.x == 0) g_stats[t] = 0.f;
    int tile = blockIdx.x;
    int b = g_tile_g[tile];
    if (b < 0) return;

    size_t bbase = ((size_t)l * BB + b) * 4096;
    const char* A1hp = (const char*)(g_A1h + (size_t)tile * 8192);
    const char* A1lp = (const char*)(g_A1l + (size_t)tile * 8192);
    const char* A2hp = (const char*)(g_A2h + (size_t)tile * 8192);
    const char* A2lp = (const char*)(g_A2l + (size_t)tile * 8192);
    const char* B1hp = (const char*)(g_B1h4 + bbase);
    const char* B1lp = (const char*)(g_B1l4 + bbase);
    const char* B2hp = (const char*)(g_B2h4 + l * 4096);
    const char* B2lp = (const char*)(g_B2l4 + l * 4096);

#define STAGE_A(G, OFF) { \
    _Pragma("unroll") \
    for (int i = 0; i < 4; i++) { \
        int lin = i * 256 + t; \
        cp16(sb + (OFF) + (lin >> 3) * 144 + (lin & 7) * 16, (G) + lin * 16); } }
#define STAGE_B(G, OFF) { \
    _Pragma("unroll") \
    for (int i = 0; i < 2; i++) { \
        int lin = i * 256 + t; \
        cp16(sb + (OFF) + (lin >> 3) * 144 + (lin & 7) * 16, (G) + lin * 16); } }

    STAGE_A(A1hp, OA0); STAGE_B(B1hp, OB0); cp_commit();   // G0
    STAGE_B(B1lp, OB1); cp_commit();                        // G1
    STAGE_A(A1lp, OA1); cp_commit();                        // G2

    uint32_t aOff = (uint32_t)((w & 3) * 32 + (lane & 15)) * 144 + ((lane >> 4) & 1) * 16;
    uint32_t bOff = (uint32_t)((w >> 2) * 32 + ((lane >> 4) & 1) * 8 + (lane & 7)) * 144
                  + ((lane >> 3) & 1) * 16;

    float acc[2][4][4];
#pragma unroll
    for (int mt = 0; mt < 2; mt++)
#pragma unroll
        for (int nt = 0; nt < 4; nt++)
#pragma unroll
            for (int j = 0; j < 4; j++) acc[mt][nt][j] = 0.f;

    // p0: A1h (A0) * B1h (B0)
    asm volatile("cp.async.wait_group 2;" ::: "memory"); __syncthreads();
    product(acc, sb + OA0 + aOff, sb + OB0 + bOff);
    // p1: A1h (A0) * B1l (B1)
    asm volatile("cp.async.wait_group 1;" ::: "memory"); __syncthreads();
    product(acc, sb + OA0 + aOff, sb + OB1 + bOff);
    __syncthreads();                         // WAR: A0 free
    STAGE_A(A2hp, OA0); cp_commit();         // G3
    // p2: A1l (A1) * B1h (B0)   [needs G2; pending after wait: G3]
    asm volatile("cp.async.wait_group 1;" ::: "memory"); __syncthreads();
    product(acc, sb + OA1 + aOff, sb + OB0 + bOff);
    __syncthreads();                         // WAR: B0, A1 free
    STAGE_B(B2hp, OB0); cp_commit();         // G4
    STAGE_B(B2lp, OB1); STAGE_A(A2lp, OA1); cp_commit();   // G5
    // p3: A2h (A0) * B2h (B0)   [needs G3,G4; pending after wait: G5]
    asm volatile("cp.async.wait_group 1;" ::: "memory"); __syncthreads();
    product(acc, sb + OA0 + aOff, sb + OB0 + bOff);
    // p4/p5 need G5
    asm volatile("cp.async.wait_group 0;" ::: "memory"); __syncthreads();
    product(acc, sb + OA0 + aOff, sb + OB1 + bOff);   // A2h * B2l
    product(acc, sb + OA1 + aOff, sb + OB0 + bOff);   // A2l * B2h
    __syncthreads();   // A region dead; overlay D

    // ---- write D frags (row stride 272B) ----
    int wm = w & 3, wn = w >> 2;
    int g = lane >> 2, tig = lane & 3;
#pragma unroll
    for (int mt = 0; mt < 2; mt++) {
        int r0 = wm * 32 + mt * 16 + g;
#pragma unroll
        for (int nt = 0; nt < 4; nt++) {
            int c = wn * 32 + nt * 8 + tig * 2;
            *(float2*)(sm + OD + r0 * 272 + c * 4) = make_float2(acc[mt][nt][0], acc[mt][nt][1]);
            *(float2*)(sm + OD + (r0 + 8) * 272 + c * 4) = make_float2(acc[mt][nt][2], acc[mt][nt][3]);
        }
    }
    __syncthreads();

    // ---- epilogue: 2 threads per edge ----
    int edge = t >> 1, half = t & 1;
    int slot = tile * 128 + edge;
    int srcn = g_ssrc[slot];
    if (srcn >= 0) {
        int dstn = g_sdst[slot];
        const float* Dr = (const float*)(sm + OD + edge * 272 + half * 128);
        const float* xr = xcur + (size_t)srcn * 64 + half * 32;
        const float* br = g_bc4 + l * 64 + half * 32;
        float* dp = g_agg + (size_t)dstn * 64 + half * 32;
#pragma unroll
        for (int q = 0; q < 8; q++) {
            float4 dv = *(const float4*)(Dr + q * 4);
            float4 xv = *(const float4*)(xr + q * 4);
            float4 bc = *(const float4*)(br + q * 4);
            red_add_v4(dp + q * 4,
                       fmaxf(dv.x + bc.x + xv.x, 0.f), fmaxf(dv.y + bc.y + xv.y, 0.f),
                       fmaxf(dv.z + bc.z + xv.z, 0.f), fmaxf(dv.w + bc.w + xv.w, 0.f));
        }
    }
}

// ---------------- node kernels ----------------
__global__ __launch_bounds__(256) void nodeA_kernel(const float* __restrict__ xcur,
                                                    const float* __restrict__ W,
                                                    const float* __restrict__ bias, int l) {
    __shared__ float sW[64 * 64];
    __shared__ float sA[64 * 32];
    __shared__ float sRs[256], sRq[256];
    int t = threadIdx.x;
    int n0 = blockIdx.x * 32;
    {
        const float4* Wv = (const float4*)(W + (size_t)l * 4096);
        float4* sWv = (float4*)sW;
#pragma unroll
        for (int i = 0; i < 4; i++) sWv[t + 256 * i] = Wv[t + 256 * i];
    }
    int n_loc = t & 31, part = t >> 5;
    int k0 = part * 8;
    {
        size_t base = (size_t)(n0 + n_loc) * 64 + k0;
        float4 x0 = *(const float4*)(xcur + base);
        float4 x1 = *(const float4*)(xcur + base + 4);
        float4 a0 = *(const float4*)(g_agg + base);
        float4 a1 = *(const float4*)(g_agg + base + 4);
        *(float4*)(g_agg + base) = make_float4(0.f, 0.f, 0.f, 0.f);
        *(float4*)(g_agg + base + 4) = make_float4(0.f, 0.f, 0.f, 0.f);
        sA[(k0 + 0) * 32 + n_loc] = x0.x + a0.x;
        sA[(k0 + 1) * 32 + n_loc] = x0.y + a0.y;
        sA[(k0 + 2) * 32 + n_loc] = x0.z + a0.z;
        sA[(k0 + 3) * 32 + n_loc] = x0.w + a0.w;
        sA[(k0 + 4) * 32 + n_loc] = x1.x + a1.x;
        sA[(k0 + 5) * 32 + n_loc] = x1.y + a1.y;
        sA[(k0 + 6) * 32 + n_loc] = x1.z + a1.z;
        sA[(k0 + 7) * 32 + n_loc] = x1.w + a1.w;
    }
    __syncthreads();

    int tx = t & 63, ty = t >> 6;
    unsigned long long acc[4] = {0ull, 0ull, 0ull, 0ull};
#pragma unroll 8
    for (int k = 0; k < 64; k++) {
        float w = sW[k * 64 + tx];
        unsigned long long w2 = pack2(w, w);
        const ulonglong2* ap = (const ulonglong2*)(sA + k * 32 + ty * 8);
        ulonglong2 a01 = ap[0];
        ulonglong2 a23 = ap[1];
        ffma2(acc[0], a01.x, w2);
        ffma2(acc[1], a01.y, w2);
        ffma2(acc[2], a23.x, w2);
        ffma2(acc[3], a23.y, w2);
    }
    float bb = bias[l * 64 + tx];
    float s = 0.f, q = 0.f;
#pragma unroll
    for (int p = 0; p < 4; p++) {
        float2 v = unpack2(acc[p]);
        int na = ty * 8 + p * 2;
        float yA = v.x + bb, yB = v.y + bb;
        g_y1[(size_t)(n0 + na) * 64 + tx] = yA;
        g_y1[(size_t)(n0 + na + 1) * 64 + tx] = yB;
        s += yA + yB;
        q += yA * yA + yB * yB;
    }
    sRs[t] = s;
    sRq[t] = q;
    __syncthreads();
    if (t < 64) {
        s = sRs[t] + sRs[64 + t] + sRs[128 + t] + sRs[192 + t];
        q = sRq[t] + sRq[64 + t] + sRq[128 + t] + sRq[192 + t];
        atomicAdd(&g_stats[t], s);
        atomicAdd(&g_stats[64 + t], q);
    }
}

__global__ __launch_bounds__(256) void nodeB_kernel(const float* __restrict__ W,
                                                    const float* __restrict__ bias,
                                                    const float* __restrict__ bg,
                                                    const float* __restrict__ bnb, int l) {
    __shared__ float sW[64 * 64];
    __shared__ float sA[64 * 32];
    __shared__ float sSc[64], sSh[64];
    __shared__ float sRs[256], sRq[256];
    int t = threadIdx.x;
    int n0 = blockIdx.x * 32;
    {
        const float4* Wv = (const float4*)(W + (size_t)l * 4096);
        float4* sWv = (float4*)sW;
#pragma unroll
        for (int i = 0; i < 4; i++) sWv[t + 256 * i] = Wv[t + 256 * i];
    }
    if (t < 64) {
        float mu = g_stats[t] * (1.0f / NN);
        float var = g_stats[64 + t] * (1.0f / NN) - mu * mu;
        float rs = rsqrtf(var + EPS_BN);
        float sc = rs * bg[l * 64 + t];
        sSc[t] = sc;
        sSh[t] = bnb[l * 64 + t] - mu * sc;
    }
    __syncthreads();
    int n_loc = t & 31, part = t >> 5;
    int k0 = part * 8;
    {
        size_t base = (size_t)(n0 + n_loc) * 64 + k0;
        float4 y0 = *(const float4*)(g_y1 + base);
        float4 y1v = *(const float4*)(g_y1 + base + 4);
        sA[(k0 + 0) * 32 + n_loc] = fmaxf(y0.x * sSc[k0 + 0] + sSh[k0 + 0], 0.f);
        sA[(k0 + 1) * 32 + n_loc] = fmaxf(y0.y * sSc[k0 + 1] + sSh[k0 + 1], 0.f);
        sA[(k0 + 2) * 32 + n_loc] = fmaxf(y0.z * sSc[k0 + 2] + sSh[k0 + 2], 0.f);
        sA[(k0 + 3) * 32 + n_loc] = fmaxf(y0.w * sSc[k0 + 3] + sSh[k0 + 3], 0.f);
        sA[(k0 + 4) * 32 + n_loc] = fmaxf(y1v.x * sSc[k0 + 4] + sSh[k0 + 4], 0.f);
        sA[(k0 + 5) * 32 + n_loc] = fmaxf(y1v.y * sSc[k0 + 5] + sSh[k0 + 5], 0.f);
        sA[(k0 + 6) * 32 + n_loc] = fmaxf(y1v.z * sSc[k0 + 6] + sSh[k0 + 6], 0.f);
        sA[(k0 + 7) * 32 + n_loc] = fmaxf(y1v.w * sSc[k0 + 7] + sSh[k0 + 7], 0.f);
    }
    __syncthreads();

    int tx = t & 63, ty = t >> 6;
    unsigned long long acc[4] = {0ull, 0ull, 0ull, 0ull};
#pragma unroll 8
    for (int k = 0; k < 64; k++) {
        float w = sW[k * 64 + tx];
        unsigned long long w2 = pack2(w, w);
        const ulonglong2* ap = (const ulonglong2*)(sA + k * 32 + ty * 8);
        ulonglong2 a01 = ap[0];
        ulonglong2 a23 = ap[1];
        ffma2(acc[0], a01.x, w2);
        ffma2(acc[1], a01.y, w2);
        ffma2(acc[2], a23.x, w2);
        ffma2(acc[3], a23.y, w2);
    }
    float bb = bias[l * 64 + tx];
    float s = 0.f, q = 0.f;
#pragma unroll
    for (int p = 0; p < 4; p++) {
        float2 v = unpack2(acc[p]);
        int na = ty * 8 + p * 2;
        float yA = v.x + bb, yB = v.y + bb;
        g_y2[(size_t)(n0 + na) * 64 + tx] = yA;
        g_y2[(size_t)(n0 + na + 1) * 64 + tx] = yB;
        s += yA + yB;
        q += yA * yA + yB * yB;
    }
    sRs[t] = s;
    sRq[t] = q;
    __syncthreads();
    if (t < 64) {
        s = sRs[t] + sRs[64 + t] + sRs[128 + t] + sRs[192 + t];
        q = sRq[t] + sRq[64 + t] + sRq[128 + t] + sRq[192 + t];
        atomicAdd(&g_stats[128 + t], s);
        atomicAdd(&g_stats[192 + t], q);
    }
}

// x_out = BN2(y2) [+ relu unless last layer]; float4-vectorized
__global__ void bn_apply_kernel(const float* __restrict__ bg, const float* __restrict__ bnb,
                                float* __restrict__ xout, int l, int do_relu) {
    int i = blockIdx.x * 256 + threadIdx.x;   // < N*16 float4
    int h4 = (i & 15) * 4;
    float4 y = ((const float4*)g_y2)[i];
    float sc[4], sh[4];
#pragma unroll
    for (int j = 0; j < 4; j++) {
        int h = h4 + j;
        float mu = g_stats[128 + h] * (1.0f / NN);
        float var = g_stats[192 + h] * (1.0f / NN) - mu * mu;
        float rs = rsqrtf(var + EPS_BN);
        sc[j] = rs * bg[l * 64 + h];
        sh[j] = bnb[l * 64 + h] - mu * sc[j];
    }
    float4 v;
    v.x = y.x * sc[0] + sh[0];
    v.y = y.y * sc[1] + sh[1];
    v.z = y.z * sc[2] + sh[2];
    v.w = y.w * sc[3] + sh[3];
    if (do_relu) {
        v.x = fmaxf(v.x, 0.f); v.y = fmaxf(v.y, 0.f);
        v.z = fmaxf(v.z, 0.f); v.w = fmaxf(v.w, 0.f);
    }
    ((float4*)xout)[i] = v;
}

__global__ void copy_pe_kernel(const float* __restrict__ pe, float* __restrict__ out) {
    size_t i = (size_t)blockIdx.x * 256 + threadIdx.x;
    ((float4*)out)[i] = ((const float4*)pe)[i];
}

// ---------------- launcher ----------------
extern "C" void kernel_launch(void* const* d_in, const int* in_sizes, int n_in,
                              void* d_out, int out_size) {
    const float* x        = (const float*)d_in[0];
    const float* pe       = (const float*)d_in[1];
    const float* Lam      = (const float*)d_in[2];
    const float* edge_attr= (const float*)d_in[3];
    const float* pw1      = (const float*)d_in[4];
    const float* pb1      = (const float*)d_in[5];
    const float* pw2      = (const float*)d_in[6];
    const float* pb2      = (const float*)d_in[7];
    const float* enc_w    = (const float*)d_in[8];
    const float* enc_b    = (const float*)d_in[9];
    const float* lin_w    = (const float*)d_in[10];
    const float* lin_b    = (const float*)d_in[11];
    const float* mw1      = (const float*)d_in[12];
    const float* mb1      = (const float*)d_in[13];
    const float* bn1g     = (const float*)d_in[14];
    const float* bn1b     = (const float*)d_in[15];
    const float* mw2      = (const float*)d_in[16];
    const float* mb2      = (const float*)d_in[17];
    const float* bn2g     = (const float*)d_in[18];
    const float* bn2b     = (const float*)d_in[19];
    const int*   ei       = (const int*)d_in[20];
    const int*   batch    = (const int*)d_in[21];
    float* out = (float*)d_out;

    float* xb = nullptr;
    cudaGetSymbolAddress((void**)&xb, g_xb);
    cudaFuncSetAttribute(edge_mma_kernel, cudaFuncAttributeMaxDynamicSharedMemorySize, SMEM_EDGE);

    k1_setup<<<6250, 256>>>(Lam, pw1, pb1, pw2, pb2, enc_w, enc_b, lin_w, lin_b);
    k2_count_wprep<<<3125 + 404, 256>>>(ei, batch);
    k3_scan_fill_convert<<<EE / 8, 256>>>(pe, edge_attr, ei, batch);

    for (int l = 0; l < LL; l++) {
        const float* xcur = (l == 0) ? x : (const float*)xb;
        float* xout = (l == LL - 1) ? out : xb;
        edge_mma_kernel<<<MAXT, 256, SMEM_EDGE>>>(xcur, l);
        nodeA_kernel<<<NN / 32, 256>>>(xcur, mw1, mb1, l);
        nodeB_kernel<<<NN / 32, 256>>>(mw2, mb2, bn1g, bn1b, l);
        bn_apply_kernel<<<NN * 16 / 256, 256>>>(bn2g, bn2b, xout, l, (l != LL - 1) ? 1 : 0);
    }
    if (out_size >= (int)(2u * NN * 64)) {
        copy_pe_kernel<<<NN * 16 / 256, 256>>>(pe, out + (size_t)NN * 64);
    }
}